// round 1
// baseline (speedup 1.0000x reference)
#include <cuda_runtime.h>
#include <cstdint>

#define N_BITS 108
#define N_OUT  7

__global__ __launch_bounds__(256)
void lzd108_kernel(const float* __restrict__ X, float* __restrict__ out, int n_rows) {
    int row = blockIdx.x * blockDim.x + threadIdx.x;
    if (row >= n_rows) return;

    // Row is 108 floats = 432 bytes, 16B-aligned -> float4 loads are legal.
    const float4* p = reinterpret_cast<const float4*>(X + (size_t)row * N_BITS);

    int pos = N_BITS;  // 108 sentinel = all-zero row

    // Scan floats [0, 104) in 8-float (32B = one L2 sector) chunks.
    // Early break: lanes that found their first 1 stop issuing loads, so
    // untouched sectors are never fetched from DRAM (sparse input -> ~3x less traffic).
    #pragma unroll 1
    for (int k = 0; k < 13; ++k) {
        float4 a = __ldg(p + 2 * k);
        float4 b = __ldg(p + 2 * k + 1);
        // values are exactly 0.0f or 1.0f -> sum is nonzero iff any bit set
        float s = (a.x + a.y + a.z + a.w) + (b.x + b.y + b.z + b.w);
        if (s != 0.0f) {
            int base = 8 * k;
            if      (a.x != 0.0f) pos = base + 0;
            else if (a.y != 0.0f) pos = base + 1;
            else if (a.z != 0.0f) pos = base + 2;
            else if (a.w != 0.0f) pos = base + 3;
            else if (b.x != 0.0f) pos = base + 4;
            else if (b.y != 0.0f) pos = base + 5;
            else if (b.z != 0.0f) pos = base + 6;
            else                  pos = base + 7;
            break;
        }
    }

    // Tail: floats [104, 108)
    if (pos == N_BITS) {
        float4 a = __ldg(p + 26);
        if      (a.x != 0.0f) pos = 104;
        else if (a.y != 0.0f) pos = 105;
        else if (a.z != 0.0f) pos = 106;
        else if (a.w != 0.0f) pos = 107;
        // else stays 108 (all-zero row); 108 = 1101100b matches LZC_108
    }

    float* o = out + (size_t)row * N_OUT;
    #pragma unroll
    for (int j = 0; j < N_OUT; ++j) {
        o[j] = (float)((pos >> (6 - j)) & 1);
    }
}

extern "C" void kernel_launch(void* const* d_in, const int* in_sizes, int n_in,
                              void* d_out, int out_size) {
    const float* X = (const float*)d_in[0];
    float* out = (float*)d_out;
    int n_rows = in_sizes[0] / N_BITS;

    int threads = 256;
    int blocks = (n_rows + threads - 1) / threads;
    lzd108_kernel<<<blocks, threads>>>(X, out, n_rows);
}

// round 2
// speedup vs baseline: 1.1918x; 1.1918x over previous
#include <cuda_runtime.h>
#include <cstdint>

#define N_BITS 108
#define N_OUT  7

// Row = 108 floats = 432 B = 27 uint4 (16B-aligned).
// Values are exactly 0.0f (0x00000000) or 1.0f (0x3F800000):
// (word >> 29) & 1 extracts the logical bit.

__global__ __launch_bounds__(256)
void lzd108_kernel(const uint4* __restrict__ X, float* __restrict__ out, int n_rows) {
    int row = blockIdx.x * blockDim.x + threadIdx.x;
    if (row >= n_rows) return;

    const uint4* p = X + (size_t)row * 27;

    int pos = N_BITS;  // 108 sentinel (all-zero row); 108 = 1101100b == LZC_108

    // 3 rounds of 128B (32 floats) each: floats [0,32), [32,64), [64,96).
    // 8 independent LDG.128 per round -> MLP=8, only up to 4 dependent rounds total.
    #pragma unroll 1
    for (int r = 0; r < 3; ++r) {
        uint4 w[8];
        #pragma unroll
        for (int j = 0; j < 8; ++j) {
            w[j] = __ldg(p + r * 8 + j);
        }
        unsigned m = 0;
        #pragma unroll
        for (int j = 0; j < 8; ++j) {
            m |= ((w[j].x >> 29) & 1u) << (4 * j + 0);
            m |= ((w[j].y >> 29) & 1u) << (4 * j + 1);
            m |= ((w[j].z >> 29) & 1u) << (4 * j + 2);
            m |= ((w[j].w >> 29) & 1u) << (4 * j + 3);
        }
        if (m != 0u) {
            pos = r * 32 + (__ffs(m) - 1);
            break;
        }
    }

    // Tail round: floats [96, 108) = 3 uint4 = 48B.
    if (pos == N_BITS) {
        uint4 w0 = __ldg(p + 24);
        uint4 w1 = __ldg(p + 25);
        uint4 w2 = __ldg(p + 26);
        unsigned m = 0;
        m |= ((w0.x >> 29) & 1u) << 0;
        m |= ((w0.y >> 29) & 1u) << 1;
        m |= ((w0.z >> 29) & 1u) << 2;
        m |= ((w0.w >> 29) & 1u) << 3;
        m |= ((w1.x >> 29) & 1u) << 4;
        m |= ((w1.y >> 29) & 1u) << 5;
        m |= ((w1.z >> 29) & 1u) << 6;
        m |= ((w1.w >> 29) & 1u) << 7;
        m |= ((w2.x >> 29) & 1u) << 8;
        m |= ((w2.y >> 29) & 1u) << 9;
        m |= ((w2.z >> 29) & 1u) << 10;
        m |= ((w2.w >> 29) & 1u) << 11;
        if (m != 0u) {
            pos = 96 + (__ffs(m) - 1);
        }
    }

    float* o = out + (size_t)row * N_OUT;
    #pragma unroll
    for (int j = 0; j < N_OUT; ++j) {
        o[j] = (float)((pos >> (6 - j)) & 1);
    }
}

extern "C" void kernel_launch(void* const* d_in, const int* in_sizes, int n_in,
                              void* d_out, int out_size) {
    const uint4* X = (const uint4*)d_in[0];
    float* out = (float*)d_out;
    int n_rows = in_sizes[0] / N_BITS;

    int threads = 256;
    int blocks = (n_rows + threads - 1) / threads;
    lzd108_kernel<<<blocks, threads>>>(X, out, n_rows);
}

// round 3
// speedup vs baseline: 1.1961x; 1.0036x over previous
#include <cuda_runtime.h>
#include <cstdint>

#define N_BITS 108
#define N_OUT  7
#define TPB    256

// Row = 108 floats = 432 B = 27 uint4 (16B-aligned, 432 = 27*16).
// Values are exactly 0.0f (0x00000000) or 1.0f (0x3F800000):
// (word >> 29) & 1 extracts the logical bit.

__device__ __forceinline__ unsigned mask4(uint4 w, int sh) {
    return (((w.x >> 29) & 1u) << sh)
         | (((w.y >> 29) & 1u) << (sh + 1))
         | (((w.z >> 29) & 1u) << (sh + 2))
         | (((w.w >> 29) & 1u) << (sh + 3));
}

__global__ __launch_bounds__(TPB)
void lzd108_kernel(const uint4* __restrict__ X, float* __restrict__ out, int n_rows) {
    __shared__ float s[TPB * N_OUT];

    int row = blockIdx.x * TPB + threadIdx.x;

    int pos = N_BITS;  // 108 sentinel (all-zero row); 108 = 1101100b == LZC_108

    if (row < n_rows) {
        const uint4* p = X + (size_t)row * 27;

        // Geometric round schedule (bits): 8, 8, 16, 32, 44.
        // Per-lane predicated loads: lanes that found their bit stop fetching,
        // so unneeded sectors never leave DRAM.
        // Round 0: bits [0,8) — 32 B
        unsigned m0 = mask4(__ldcs(p + 0), 0) | mask4(__ldcs(p + 1), 4);
        if (m0) {
            pos = __ffs(m0) - 1;
        } else {
            // Round 1: bits [8,16) — 32 B
            unsigned m1 = mask4(__ldcs(p + 2), 0) | mask4(__ldcs(p + 3), 4);
            if (m1) {
                pos = 8 + __ffs(m1) - 1;
            } else {
                // Round 2: bits [16,32) — 64 B
                unsigned m2 = 0;
                #pragma unroll
                for (int j = 0; j < 4; ++j) m2 |= mask4(__ldcs(p + 4 + j), 4 * j);
                if (m2) {
                    pos = 16 + __ffs(m2) - 1;
                } else {
                    // Round 3: bits [32,64) — 128 B
                    uint4 w[8];
                    #pragma unroll
                    for (int j = 0; j < 8; ++j) w[j] = __ldcs(p + 8 + j);
                    unsigned m3 = 0;
                    #pragma unroll
                    for (int j = 0; j < 8; ++j) m3 |= mask4(w[j], 4 * j);
                    if (m3) {
                        pos = 32 + __ffs(m3) - 1;
                    } else {
                        // Round 4: bits [64,108) — 176 B (11 uint4 = 44 bits)
                        uint4 v[11];
                        #pragma unroll
                        for (int j = 0; j < 11; ++j) v[j] = __ldcs(p + 16 + j);
                        unsigned long long m4 = 0;
                        #pragma unroll
                        for (int j = 0; j < 11; ++j)
                            m4 |= (unsigned long long)mask4(v[j], 0) << (4 * j);
                        if (m4) pos = 64 + __ffsll(m4) - 1;
                        // else stays 108
                    }
                }
            }
        }
    }

    // Stage outputs in smem (stride-7 per thread: gcd(7,32)=1 -> conflict-free),
    // then write the block's 1792 floats fully coalesced.
    #pragma unroll
    for (int j = 0; j < N_OUT; ++j)
        s[threadIdx.x * N_OUT + j] = (float)((pos >> (6 - j)) & 1);

    __syncthreads();

    size_t block_base = (size_t)blockIdx.x * (TPB * N_OUT);
    size_t total = (size_t)n_rows * N_OUT;
    #pragma unroll
    for (int i = 0; i < N_OUT; ++i) {
        size_t gi = block_base + i * TPB + threadIdx.x;
        if (gi < total) out[gi] = s[i * TPB + threadIdx.x];
    }
}

extern "C" void kernel_launch(void* const* d_in, const int* in_sizes, int n_in,
                              void* d_out, int out_size) {
    const uint4* X = (const uint4*)d_in[0];
    float* out = (float*)d_out;
    int n_rows = in_sizes[0] / N_BITS;

    int blocks = (n_rows + TPB - 1) / TPB;
    lzd108_kernel<<<blocks, TPB>>>(X, out, n_rows);
}

// round 4
// speedup vs baseline: 1.2026x; 1.0054x over previous
#include <cuda_runtime.h>
#include <cstdint>

#define N_BITS 108
#define N_OUT  7
#define TPB    256

// Row = 108 floats = 432 B = 27 uint4. 432 mod 32 = 16, so odd rows start
// 16 B into a 32 B DRAM sector. Round boundaries are chosen per row parity so
// every round covers whole sectors -> no split-sector DRAM waste.
// Values are exactly 0.0f / 1.0f: (word >> 29) & 1 extracts the bit.

__device__ __forceinline__ unsigned mask4(uint4 w, int sh) {
    return (((w.x >> 29) & 1u) << sh)
         | (((w.y >> 29) & 1u) << (sh + 1))
         | (((w.z >> 29) & 1u) << (sh + 2))
         | (((w.w >> 29) & 1u) << (sh + 3));
}

__global__ __launch_bounds__(TPB)
void lzd108_kernel(const uint4* __restrict__ X, float* __restrict__ out, int n_rows) {
    __shared__ float s[TPB * N_OUT];

    int row = blockIdx.x * TPB + threadIdx.x;
    int pos = N_BITS;  // 108 = 1101100b == LZC_108 sentinel (all-zero row)

    if (row < n_rows) {
        const uint4* p = X + (size_t)row * 27;
        int odd = row & 1;  // odd rows: first sector holds only bits [0,4)

        // Round 0: first sector. even: p[0..1] (8 bits); odd: p[0] (4 bits).
        unsigned m0 = mask4(__ldcs(p), 0);
        if (!odd) m0 |= mask4(__ldcs(p + 1), 4);
        if (m0) {
            pos = __ffs(m0) - 1;
        } else {
            // Round 1: 1 sector (8 bits). start uint4 = 2-odd.
            int i1 = 2 - odd;
            unsigned m1 = mask4(__ldcs(p + i1), 0) | mask4(__ldcs(p + i1 + 1), 4);
            if (m1) {
                pos = 4 * i1 + __ffs(m1) - 1;
            } else {
                // Round 2: 2 sectors (16 bits). start = 4-odd.
                int i2 = 4 - odd;
                unsigned m2 = 0;
                #pragma unroll
                for (int j = 0; j < 4; ++j) m2 |= mask4(__ldcs(p + i2 + j), 4 * j);
                if (m2) {
                    pos = 4 * i2 + __ffs(m2) - 1;
                } else {
                    // Round 3: 4 sectors (32 bits). start = 8-odd.
                    int i3 = 8 - odd;
                    unsigned m3 = 0;
                    #pragma unroll
                    for (int j = 0; j < 8; ++j) m3 |= mask4(__ldcs(p + i3 + j), 4 * j);
                    if (m3) {
                        pos = 4 * i3 + __ffs(m3) - 1;
                    } else {
                        // Round 4: rest of row. even: p[16..26] (44 bits);
                        // odd: p[15..26] (48 bits).
                        int i4 = 16 - odd;
                        unsigned long long m4 = 0;
                        #pragma unroll
                        for (int j = 0; j < 11; ++j)
                            m4 |= (unsigned long long)mask4(__ldcs(p + i4 + j), 0) << (4 * j);
                        if (odd)
                            m4 |= (unsigned long long)mask4(__ldcs(p + 26), 0) << 44;
                        if (m4) pos = 4 * i4 + __ffsll(m4) - 1;
                        // else stays 108
                    }
                }
            }
        }
    }

    // Stage outputs in smem (stride-7: gcd(7,32)=1 -> conflict-free), then
    // write the block's 1792 floats fully coalesced.
    #pragma unroll
    for (int j = 0; j < N_OUT; ++j)
        s[threadIdx.x * N_OUT + j] = (float)((pos >> (6 - j)) & 1);

    __syncthreads();

    size_t block_base = (size_t)blockIdx.x * (TPB * N_OUT);
    size_t total = (size_t)n_rows * N_OUT;
    #pragma unroll
    for (int i = 0; i < N_OUT; ++i) {
        size_t gi = block_base + i * TPB + threadIdx.x;
        if (gi < total) out[gi] = s[i * TPB + threadIdx.x];
    }
}

extern "C" void kernel_launch(void* const* d_in, const int* in_sizes, int n_in,
                              void* d_out, int out_size) {
    const uint4* X = (const uint4*)d_in[0];
    float* out = (float*)d_out;
    int n_rows = in_sizes[0] / N_BITS;

    int blocks = (n_rows + TPB - 1) / TPB;
    lzd108_kernel<<<blocks, TPB>>>(X, out, n_rows);
}

// round 5
// speedup vs baseline: 1.2147x; 1.0100x over previous
#include <cuda_runtime.h>
#include <cstdint>

#define N_BITS 108
#define N_OUT  7
#define TPB    256

// Row = 108 floats = 432 B = 27 uint4.
// Values are exactly 0.0f / 1.0f: (word >> 29) & 1 extracts the bit.
// Round schedule (uint4 idx): [0,4)=16 bits, [4,8)=16 bits, [8,16)=32 bits,
// [16,27)=44 bits. Depth-4 dependent chain; early-exit lanes stop loading.

__device__ __forceinline__ unsigned mask4(uint4 w, int sh) {
    return (((w.x >> 29) & 1u) << sh)
         | (((w.y >> 29) & 1u) << (sh + 1))
         | (((w.z >> 29) & 1u) << (sh + 2))
         | (((w.w >> 29) & 1u) << (sh + 3));
}

__global__ __launch_bounds__(TPB, 8)
void lzd108_kernel(const uint4* __restrict__ X, float* __restrict__ out, int n_rows) {
    __shared__ float s[TPB * N_OUT];

    int row = blockIdx.x * TPB + threadIdx.x;
    int pos = N_BITS;  // 108 = 1101100b == LZC_108 sentinel (all-zero row)

    if (row < n_rows) {
        const uint4* p = X + (size_t)row * 27;

        // Round 0: bits [0,16) — 64 B, 4 independent LDG.128
        unsigned m0 = 0;
        #pragma unroll
        for (int j = 0; j < 4; ++j) m0 |= mask4(__ldcs(p + j), 4 * j);
        if (m0) {
            pos = __ffs(m0) - 1;
        } else {
            // Round 1: bits [16,32) — 64 B
            unsigned m1 = 0;
            #pragma unroll
            for (int j = 0; j < 4; ++j) m1 |= mask4(__ldcs(p + 4 + j), 4 * j);
            if (m1) {
                pos = 16 + __ffs(m1) - 1;
            } else {
                // Round 2: bits [32,64) — 128 B
                unsigned m2 = 0;
                #pragma unroll
                for (int j = 0; j < 8; ++j) m2 |= mask4(__ldcs(p + 8 + j), 4 * j);
                if (m2) {
                    pos = 32 + __ffs(m2) - 1;
                } else {
                    // Round 3: bits [64,108) — 176 B (11 uint4, 44 bits)
                    unsigned long long m3 = 0;
                    #pragma unroll
                    for (int j = 0; j < 11; ++j)
                        m3 |= (unsigned long long)mask4(__ldcs(p + 16 + j), 0) << (4 * j);
                    if (m3) pos = 64 + __ffsll(m3) - 1;
                    // else stays 108
                }
            }
        }
    }

    // Stage outputs in smem (stride-7: gcd(7,32)=1 -> conflict-free), then
    // write the block's 1792 floats fully coalesced.
    #pragma unroll
    for (int j = 0; j < N_OUT; ++j)
        s[threadIdx.x * N_OUT + j] = (float)((pos >> (6 - j)) & 1);

    __syncthreads();

    size_t block_base = (size_t)blockIdx.x * (TPB * N_OUT);
    size_t total = (size_t)n_rows * N_OUT;
    #pragma unroll
    for (int i = 0; i < N_OUT; ++i) {
        size_t gi = block_base + i * TPB + threadIdx.x;
        if (gi < total) out[gi] = s[i * TPB + threadIdx.x];
    }
}

extern "C" void kernel_launch(void* const* d_in, const int* in_sizes, int n_in,
                              void* d_out, int out_size) {
    const uint4* X = (const uint4*)d_in[0];
    float* out = (float*)d_out;
    int n_rows = in_sizes[0] / N_BITS;

    int blocks = (n_rows + TPB - 1) / TPB;
    lzd108_kernel<<<blocks, TPB>>>(X, out, n_rows);
}